// round 16
// baseline (speedup 1.0000x reference)
#include <cuda_runtime.h>
#include <cuda_bf16.h>
#include <cstdint>
#include <cstddef>

typedef unsigned long long u64;

#define KDIM 3072
#define FDIM 512
#define VDIM 128
#define NBATCH 32
#define NN 256
#define BN 8192
#define TEMP 11.3137084989847606f  // sqrt(128)

// ---------------- device scratch ----------------
static __device__ float g_bc[VDIM];
static __device__ float g_wcp[4][KDIM * VDIM];
static __device__ __nv_bfloat16 g_Wc_hi[(size_t)VDIM * KDIM];   // [v][k]
static __device__ __nv_bfloat16 g_Wc_lo[(size_t)VDIM * KDIM];   // [v][k]
static __device__ float g_vp[2][(size_t)BN * VDIM];
static __device__ __nv_bfloat16 g_fnh[(size_t)BN * VDIM];       // fn hi (bf16)
static __device__ __nv_bfloat16 g_fnl[(size_t)BN * VDIM];       // fn lo (bf16)
static __device__ uint32_t g_M1T[NBATCH * 8 * NN];  // bit j = d1[b][(kw*32+j)*NN+i] != 0
static __device__ uint32_t g_M2T[NBATCH * 8 * NN];  // bit j = d2[b][(kw*32+j)*NN+i] != 0
static __device__ uint32_t g_M2R[NBATCH * 8 * NN];  // bit j = d2[b][i*NN + kw*32+j] != 0
static __device__ float g_F1[NBATCH * NN];
static __device__ float g_F2[NBATCH * NN];
static __device__ float g_lp2[NBATCH * 8];
static __device__ unsigned int g_cmb[128];          // per-M-tile combine counters
static __device__ unsigned int g_wcc[24];           // per-Wc-tile finish counters
static __device__ unsigned int g_bat[NBATCH];       // per-batch stats barrier
static __device__ unsigned int g_ctr;               // loss final counter

// ---------------- packed f32x2 helpers (SIMT GEMMs) ----------------
__device__ __forceinline__ u64 splat2(float a) {
    u64 r; asm("mov.b64 %0,{%1,%1};" : "=l"(r) : "f"(a)); return r;
}
__device__ __forceinline__ void ffma2(u64& c, u64 a, u64 b) {
    asm("fma.rn.f32x2 %0,%1,%2,%0;" : "+l"(c) : "l"(a), "l"(b));
}
__device__ __forceinline__ float2 unpack2(u64 c) {
    float2 r; asm("mov.b64 {%0,%1},%2;" : "=f"(r.x), "=f"(r.y) : "l"(c)); return r;
}

// ---------------- mma.sync helpers (plain PTX, sm_80+) ----------------
__device__ __forceinline__ uint32_t smem_u32(const void* p) {
    uint32_t a;
    asm("{ .reg .u64 t; cvta.to.shared.u64 t, %1; cvt.u32.u64 %0, t; }" : "=r"(a) : "l"(p));
    return a;
}
__device__ __forceinline__ uint32_t swz(uint32_t o) { return o ^ ((o >> 3) & 0x70); }

__device__ __forceinline__ void ldsm4(uint32_t& r0, uint32_t& r1, uint32_t& r2, uint32_t& r3,
                                      uint32_t addr) {
    asm volatile("ldmatrix.sync.aligned.m8n8.x4.shared.b16 {%0,%1,%2,%3}, [%4];"
                 : "=r"(r0), "=r"(r1), "=r"(r2), "=r"(r3) : "r"(addr));
}
__device__ __forceinline__ void mma16816(float* c, const uint32_t* a, uint32_t b0, uint32_t b1) {
    asm volatile("mma.sync.aligned.m16n8k16.row.col.f32.bf16.bf16.f32 "
                 "{%0,%1,%2,%3}, {%4,%5,%6,%7}, {%8,%9}, {%0,%1,%2,%3};"
                 : "+f"(c[0]), "+f"(c[1]), "+f"(c[2]), "+f"(c[3])
                 : "r"(a[0]), "r"(a[1]), "r"(a[2]), "r"(a[3]), "r"(b0), "r"(b1));
}
__device__ __forceinline__ void cp16(uint32_t saddr, const void* gptr) {
    asm volatile("cp.async.cg.shared.global [%0], [%1], 16;"
                 :: "r"(saddr), "l"(__cvta_generic_to_global(gptr)) : "memory");
}
__device__ __forceinline__ void cp_commit() {
    asm volatile("cp.async.commit_group;" ::: "memory");
}
__device__ __forceinline__ void cp_wait0() {
    asm volatile("cp.async.wait_group 0;" ::: "memory");
}

// ---------------- front: folded bias + counters + mask packing (ballot M2R) ----------------
// grid 257: bid 0 = bc + counters; bid 1..256 = (batch, kw) packing
__global__ void __launch_bounds__(256) k_front(const float* __restrict__ fc1_w,
                                               const float* __restrict__ conv_b,
                                               const float* __restrict__ fc1_b,
                                               const float* __restrict__ d1,
                                               const float* __restrict__ d2) {
    int bid = blockIdx.x;
    if (bid == 0) {
        int v = threadIdx.x;
        if (v < 128) {
            float s = fc1_b[v];
            for (int o = 0; o < FDIM; o++) s += fc1_w[v * FDIM + o] * conv_b[o];
            g_bc[v] = s;
            g_cmb[v] = 0;
        } else if (v < 160) {
            g_bat[v - 128] = 0;
        } else if (v == 160) {
            g_ctr = 0;
        } else if (v < 185) {
            g_wcc[v - 161] = 0;
        }
    } else {
        int idx2 = bid - 1;                          // 0..255
        int b = idx2 >> 3, kw = idx2 & 7;
        int i = threadIdx.x;                         // 0..255
        int lane = i & 31, w = i >> 5;
        const float* D1 = d1 + (size_t)b * NN * NN;
        const float* D2 = d2 + (size_t)b * NN * NN;
        uint32_t m1 = 0, m2 = 0;
#pragma unroll 8
        for (int j = 0; j < 32; j++) {
            size_t off = (size_t)(kw * 32 + j) * NN + i;
            m1 |= (D1[off] != 0.0f ? 1u : 0u) << j;
            m2 |= (D2[off] != 0.0f ? 1u : 0u) << j;
        }
        g_M1T[b * 2048 + kw * 256 + i] = m1;
        g_M2T[b * 2048 + kw * 256 + i] = m2;
        // M2R via ballot bit-transpose: warp w holds columns w*32..w*32+31 of this 32-row slab.
        // ballot of bit jj across warp w = word with bit l = d2[kw*32+jj][w*32+l]
        //   -> M2R[b][kw'=w][i = kw*32 + jj]
        uint32_t mine = 0;
#pragma unroll
        for (int jj = 0; jj < 32; jj++) {
            uint32_t bal = __ballot_sync(0xffffffffu, (m2 >> jj) & 1u);
            if (lane == jj) mine = bal;
        }
        g_M2R[b * 2048 + w * 256 + kw * 32 + lane] = mine;
    }
}

// ---------------- Wc GEMM (+fused finish): part[k3][v] = sum_o conv_w[o][k3]*fc1_w[v][o] ----------------
// grid (24, 4): 128 k3-rows x 128 v, split-K 4 (128 o each). B read directly from fc1_w (transposed load).
__global__ void __launch_bounds__(256) k_wc_gemm(const float* __restrict__ conv_w,
                                                 const float* __restrict__ fc1_w) {
    __shared__ float As[2][16][128];
    __shared__ float Bs[2][16][136];
    __shared__ float ts[16][132];
    int tid = threadIdx.x;
    int mb = blockIdx.x * 128;
    int ks = blockIdx.y;
    int tx = tid & 15, ty = tid >> 4;
    int lo = tid >> 5, lq = tid & 31;
    const float* gA = conv_w + (size_t)(ks * 128) * KDIM + mb;
    int bv = tid >> 1, bh = tid & 1;
    const float* gB = fc1_w + (size_t)bv * FDIM + ks * 128 + bh * 8;
    float4 pa0, pa1, pb0, pb1;
    auto loadG = [&](int it) {
        pa0 = *(const float4*)(gA + (size_t)(it * 16 + lo) * KDIM + lq * 4);
        pa1 = *(const float4*)(gA + (size_t)(it * 16 + lo + 8) * KDIM + lq * 4);
        pb0 = *(const float4*)(gB + it * 16);
        pb1 = *(const float4*)(gB + it * 16 + 4);
    };
    auto storeS = [&](int buf) {
        *(float4*)&As[buf][lo][lq * 4] = pa0;
        *(float4*)&As[buf][lo + 8][lq * 4] = pa1;
        Bs[buf][bh * 8 + 0][bv] = pb0.x;  Bs[buf][bh * 8 + 1][bv] = pb0.y;
        Bs[buf][bh * 8 + 2][bv] = pb0.z;  Bs[buf][bh * 8 + 3][bv] = pb0.w;
        Bs[buf][bh * 8 + 4][bv] = pb1.x;  Bs[buf][bh * 8 + 5][bv] = pb1.y;
        Bs[buf][bh * 8 + 6][bv] = pb1.z;  Bs[buf][bh * 8 + 7][bv] = pb1.w;
    };
    loadG(0); storeS(0); __syncthreads();
    u64 c[32];
#pragma unroll
    for (int i = 0; i < 32; i++) c[i] = 0ull;
    const int NIT = 8;   // 128 o's / 16
    for (int it = 0; it < NIT; ++it) {
        int cur = it & 1;
        if (it + 1 < NIT) loadG(it + 1);
#pragma unroll
        for (int kk = 0; kk < 16; kk++) {
            float4 af0 = *(float4*)&As[cur][kk][ty * 8];
            float4 af1 = *(float4*)&As[cur][kk][ty * 8 + 4];
            float4 bf0 = *(float4*)&Bs[cur][kk][tx * 8];
            float4 bf1 = *(float4*)&Bs[cur][kk][tx * 8 + 4];
            u64 b[4] = { *(u64*)&bf0.x, *(u64*)&bf0.z, *(u64*)&bf1.x, *(u64*)&bf1.z };
            float a[8] = { af0.x, af0.y, af0.z, af0.w, af1.x, af1.y, af1.z, af1.w };
#pragma unroll
            for (int mi = 0; mi < 8; mi++) {
                u64 as = splat2(a[mi]);
#pragma unroll
                for (int p = 0; p < 4; p++) ffma2(c[mi * 4 + p], as, b[p]);
            }
        }
        if (it + 1 < NIT) { storeS((it + 1) & 1); __syncthreads(); }
    }
    float* out = g_wcp[ks];
#pragma unroll
    for (int mi = 0; mi < 8; mi++) {
        float2* orow = (float2*)(out + (size_t)(mb + ty * 8 + mi) * VDIM);
#pragma unroll
        for (int p = 0; p < 4; p++) orow[tx * 4 + p] = unpack2(c[mi * 4 + p]);
    }

    // fused finish: 4th-finishing split-K CTA for this tile combines + converts
    __threadfence();
    __shared__ unsigned int rk;
    if (tid == 0) rk = atomicAdd(&g_wcc[blockIdx.x], 1u);
    __syncthreads();
    if (rk == 3) {
        __threadfence();   // acquire
        for (int sub = 0; sub < 8; sub++) {
            int k0 = mb + sub * 16;
#pragma unroll
            for (int j = 0; j < 8; j++) {
                int idx = tid + 256 * j;             // 2048
                int kk = idx >> 7, v = idx & 127;
                size_t o = (size_t)(k0 + kk) * 128 + v;
                ts[kk][v] = (g_wcp[0][o] + g_wcp[1][o]) + (g_wcp[2][o] + g_wcp[3][o]);
            }
            __syncthreads();
#pragma unroll
            for (int j = 0; j < 8; j++) {
                int idx = tid + 256 * j;
                int v = idx >> 4, kk = idx & 15;
                float val = ts[kk][v];
                __nv_bfloat16 h = __float2bfloat16(val);
                __nv_bfloat16 l = __float2bfloat16(val - __bfloat162float(h));
                g_Wc_hi[(size_t)v * KDIM + k0 + kk] = h;
                g_Wc_lo[(size_t)v * KDIM + k0 + kk] = l;
            }
            __syncthreads();
        }
    }
}

// ---------------- main GEMM + fused combine/normalize epilogue ----------------
#define SMA_L 8192
#define SMB_H 16384
#define SMB_L 32768
#define BUFSZ 49152
#define SM_TOTAL_MMA (2 * BUFSZ)

__global__ void __launch_bounds__(256, 2) k_gemm_mma(const float* __restrict__ X,
                                                     float* __restrict__ f_out) {
    extern __shared__ __align__(128) char sm[];
    int tid = threadIdx.x;
    int warp = tid >> 5, lane = tid & 31;
    int wm = warp >> 2, wn = warp & 3;
    int mb = blockIdx.x * 64;
    int ksOff = blockIdx.y * 1536;
    const float* gX = X + (size_t)mb * KDIM + ksOff;

    float acc[2][2][8];
#pragma unroll
    for (int t = 0; t < 2; t++)
#pragma unroll
        for (int n = 0; n < 2; n++)
#pragma unroll
            for (int p = 0; p < 8; p++) acc[t][n][p] = 0.f;

    int aRow = tid >> 2, aQ = tid & 3;
    float4 pa[4];

    auto loadA = [&](int c) {
#pragma unroll
        for (int j = 0; j < 4; j++)
            pa[j] = *(const float4*)(gX + (size_t)aRow * KDIM + c * 64 + aQ * 16 + j * 4);
    };
    auto storeA = [&](int s) {
        char* base = sm + s * BUFSZ;
#pragma unroll
        for (int j = 0; j < 4; j++) {
            float4 v = pa[j];
            __nv_bfloat16 h0 = __float2bfloat16(v.x), h1 = __float2bfloat16(v.y);
            __nv_bfloat16 h2 = __float2bfloat16(v.z), h3 = __float2bfloat16(v.w);
            __nv_bfloat16 l0 = __float2bfloat16(v.x - __bfloat162float(h0));
            __nv_bfloat16 l1 = __float2bfloat16(v.y - __bfloat162float(h1));
            __nv_bfloat16 l2 = __float2bfloat16(v.z - __bfloat162float(h2));
            __nv_bfloat16 l3 = __float2bfloat16(v.w - __bfloat162float(h3));
            uint32_t hw0 = (uint32_t)__bfloat16_as_ushort(h0) | ((uint32_t)__bfloat16_as_ushort(h1) << 16);
            uint32_t hw1 = (uint32_t)__bfloat16_as_ushort(h2) | ((uint32_t)__bfloat16_as_ushort(h3) << 16);
            uint32_t lw0 = (uint32_t)__bfloat16_as_ushort(l0) | ((uint32_t)__bfloat16_as_ushort(l1) << 16);
            uint32_t lw1 = (uint32_t)__bfloat16_as_ushort(l2) | ((uint32_t)__bfloat16_as_ushort(l3) << 16);
            uint32_t off = swz((uint32_t)(aRow * 128 + aQ * 32 + j * 8));
            *(uint2*)(base + off) = make_uint2(hw0, hw1);
            *(uint2*)(base + SMA_L + off) = make_uint2(lw0, lw1);
        }
    };
    int bRow = tid >> 1, bQ = tid & 1;
    auto issueB = [&](int c, int s) {
        char* base = sm + s * BUFSZ;
        size_t gbyte = ((size_t)bRow * KDIM + ksOff + c * 64) * 2;
#pragma unroll
        for (int j = 0; j < 4; j++) {
            int colb = (bQ * 4 + j) * 16;
            uint32_t off = swz((uint32_t)(bRow * 128 + colb));
            cp16(smem_u32(base + SMB_H + off), (const char*)g_Wc_hi + gbyte + colb);
            cp16(smem_u32(base + SMB_L + off), (const char*)g_Wc_lo + gbyte + colb);
        }
    };

    issueB(0, 0); cp_commit();
    loadA(0); storeA(0);
    cp_wait0();
    __syncthreads();

    int aLn = lane & 15, aLu = (lane >> 4) & 1;
    int bLn = (lane & 7) + ((lane >> 4) & 1) * 8;
    int bLu = (lane >> 3) & 1;

    const int NCH = 24;
    for (int c = 0; c < NCH; c++) {
        int s = c & 1;
        if (c + 1 < NCH) { issueB(c + 1, s ^ 1); cp_commit(); loadA(c + 1); }
        uint32_t baseA_h = smem_u32(sm + s * BUFSZ);
        uint32_t baseA_l = baseA_h + SMA_L;
        uint32_t baseB_h = baseA_h + SMB_H;
        uint32_t baseB_l = baseA_h + SMB_L;
#pragma unroll
        for (int kst = 0; kst < 4; kst++) {
            uint32_t ah[2][4], al[2][4];
#pragma unroll
            for (int t = 0; t < 2; t++) {
                uint32_t aOff = swz((uint32_t)((wm * 32 + t * 16 + aLn) * 128 + kst * 32 + aLu * 16));
                ldsm4(ah[t][0], ah[t][1], ah[t][2], ah[t][3], baseA_h + aOff);
                ldsm4(al[t][0], al[t][1], al[t][2], al[t][3], baseA_l + aOff);
            }
#pragma unroll
            for (int nt = 0; nt < 2; nt++) {
                uint32_t bh0, bh1, bh2, bh3, bl0, bl1, bl2, bl3;
                uint32_t bo = swz((uint32_t)((wn * 32 + nt * 16 + bLn) * 128 + kst * 32 + bLu * 16));
                ldsm4(bh0, bh1, bh2, bh3, baseB_h + bo);
                ldsm4(bl0, bl1, bl2, bl3, baseB_l + bo);
#pragma unroll
                for (int t = 0; t < 2; t++) {
                    float* cA = acc[t][nt];
                    float* cB = acc[t][nt] + 4;
                    mma16816(cA, ah[t], bh0, bh1);
                    mma16816(cA, ah[t], bl0, bl1);
                    mma16816(cA, al[t], bh0, bh1);
                    mma16816(cB, ah[t], bh2, bh3);
                    mma16816(cB, ah[t], bl2, bl3);
                    mma16816(cB, al[t], bh2, bh3);
                }
            }
        }
        if (c + 1 < NCH) { storeA(s ^ 1); cp_wait0(); __syncthreads(); }
    }

    // write split-K partials
#pragma unroll
    for (int t = 0; t < 2; t++) {
        int m0 = mb + wm * 32 + t * 16 + (lane >> 2);
        float* o0 = g_vp[blockIdx.y] + (size_t)m0 * VDIM;
#pragma unroll
        for (int nt = 0; nt < 2; nt++) {
            int n = wn * 32 + nt * 16 + (lane & 3) * 2;
            *(float2*)(o0 + n) = make_float2(acc[t][nt][0], acc[t][nt][1]);
            *(float2*)(o0 + 8 * VDIM + n) = make_float2(acc[t][nt][2], acc[t][nt][3]);
            *(float2*)(o0 + n + 8) = make_float2(acc[t][nt][4], acc[t][nt][5]);
            *(float2*)(o0 + 8 * VDIM + n + 8) = make_float2(acc[t][nt][6], acc[t][nt][7]);
        }
    }

    // fused combine: second-finishing CTA sums partials + bias, normalizes, emits fn as bf16 hi/lo
    __threadfence();
    __shared__ unsigned int rank_sh;
    if (tid == 0) rank_sh = atomicAdd(&g_cmb[blockIdx.x], 1u);
    __syncthreads();
    if (rank_sh == 1) {
        __threadfence();   // acquire
        const float4 bc = *(const float4*)&g_bc[lane * 4];
#pragma unroll
        for (int r = 0; r < 8; r++) {
            int row = mb + warp * 8 + r;
            size_t base = (size_t)row * VDIM + lane * 4;
            float4 p0 = *(const float4*)&g_vp[0][base];
            float4 p1 = *(const float4*)&g_vp[1][base];
            float4 x;
            x.x = p0.x + p1.x + bc.x;
            x.y = p0.y + p1.y + bc.y;
            x.z = p0.z + p1.z + bc.z;
            x.w = p0.w + p1.w + bc.w;
            *(float4*)&f_out[base] = x;
            float ss = x.x * x.x + x.y * x.y + x.z * x.z + x.w * x.w;
#pragma unroll
            for (int o = 16; o > 0; o >>= 1) ss += __shfl_xor_sync(0xffffffffu, ss, o);
            float inv = 1.0f / fmaxf(sqrtf(ss), 1e-12f);
            x.x *= inv; x.y *= inv; x.z *= inv; x.w *= inv;
            __nv_bfloat16 h0 = __float2bfloat16(x.x), h1 = __float2bfloat16(x.y);
            __nv_bfloat16 h2 = __float2bfloat16(x.z), h3 = __float2bfloat16(x.w);
            __nv_bfloat16 l0 = __float2bfloat16(x.x - __bfloat162float(h0));
            __nv_bfloat16 l1 = __float2bfloat16(x.y - __bfloat162float(h1));
            __nv_bfloat16 l2 = __float2bfloat16(x.z - __bfloat162float(h2));
            __nv_bfloat16 l3 = __float2bfloat16(x.w - __bfloat162float(h3));
            uint32_t hw0 = (uint32_t)__bfloat16_as_ushort(h0) | ((uint32_t)__bfloat16_as_ushort(h1) << 16);
            uint32_t hw1 = (uint32_t)__bfloat16_as_ushort(h2) | ((uint32_t)__bfloat16_as_ushort(h3) << 16);
            uint32_t lw0 = (uint32_t)__bfloat16_as_ushort(l0) | ((uint32_t)__bfloat16_as_ushort(l1) << 16);
            uint32_t lw1 = (uint32_t)__bfloat16_as_ushort(l2) | ((uint32_t)__bfloat16_as_ushort(l3) << 16);
            *(uint2*)&g_fnh[base] = make_uint2(hw0, hw1);
            *(uint2*)&g_fnl[base] = make_uint2(lw0, lw1);
        }
    }
}

// ---------------- affinity via mma.sync + coalesced epilogue through smem ----------------
// grid (3, 32), 256 threads, 8 warps (4 wm x 2 wn), warp tile 32x64. K=128 in 2 chunk regions.
#define AF_AL 32768
#define AF_BH 65536
#define AF_BL 98304
#define SM_TOTAL_AFF 131072

__global__ void __launch_bounds__(256, 1) k_aff(float* __restrict__ A_out) {
    extern __shared__ __align__(128) char sm[];
    int t = blockIdx.x;                  // 0:(0,0) 1:(1,1) 2:(0,1)+mirror
    int b = blockIdx.y;
    int mbase = (t == 1) ? 128 : 0;
    int nbase = (t == 0) ? 0 : 128;
    int tid = threadIdx.x, warp = tid >> 5, lane = tid & 31;
    int wm = warp >> 1, wn = warp & 1;
    const __nv_bfloat16* fh = g_fnh + (size_t)b * NN * VDIM;
    const __nv_bfloat16* fl = g_fnl + (size_t)b * NN * VDIM;

    {
        int row = tid >> 1, ch = tid & 1;
        const uint4* sAh = (const uint4*)(fh + (size_t)(mbase + row) * VDIM + ch * 64);
        const uint4* sAl = (const uint4*)(fl + (size_t)(mbase + row) * VDIM + ch * 64);
        const uint4* sBh = (const uint4*)(fh + (size_t)(nbase + row) * VDIM + ch * 64);
        const uint4* sBl = (const uint4*)(fl + (size_t)(nbase + row) * VDIM + ch * 64);
#pragma unroll
        for (int j = 0; j < 8; j++) {
            uint32_t off = (uint32_t)(ch * 16384) + swz((uint32_t)(row * 128 + j * 16));
            *(uint4*)(sm + off) = sAh[j];
            *(uint4*)(sm + AF_AL + off) = sAl[j];
            *(uint4*)(sm + AF_BH + off) = sBh[j];
            *(uint4*)(sm + AF_BL + off) = sBl[j];
        }
    }
    __syncthreads();

    float acc[2][4][8];
#pragma unroll
    for (int tt = 0; tt < 2; tt++)
#pragma unroll
        for (int n = 0; n < 4; n++)
#pragma unroll
            for (int p = 0; p < 8; p++) acc[tt][n][p] = 0.f;

    uint32_t ahb = smem_u32(sm);
    int aLn = lane & 15, aLu = (lane >> 4) & 1;
    int bLn = (lane & 7) + ((lane >> 4) & 1) * 8;
    int bLu = (lane >> 3) & 1;

#pragma unroll
    for (int kst = 0; kst < 8; kst++) {
        uint32_t chOff = (uint32_t)((kst >> 2) * 16384);
        int kk = kst & 3;
        uint32_t ah[2][4], al[2][4];
#pragma unroll
        for (int tt = 0; tt < 2; tt++) {
            uint32_t aOff = chOff + swz((uint32_t)((wm * 32 + tt * 16 + aLn) * 128 + kk * 32 + aLu * 16));
            ldsm4(ah[tt][0], ah[tt][1], ah[tt][2], ah[tt][3], ahb + aOff);
            ldsm4(al[tt][0], al[tt][1], al[tt][2], al[tt][3], ahb + AF_AL + aOff);
        }
#pragma unroll
        for (int ng = 0; ng < 4; ng++) {
            uint32_t bo = chOff + swz((uint32_t)((wn * 64 + ng * 16 + bLn) * 128 + kk * 32 + bLu * 16));
            uint32_t bh0, bh1, bh2, bh3, bl0, bl1, bl2, bl3;
            ldsm4(bh0, bh1, bh2, bh3, ahb + AF_BH + bo);
            ldsm4(bl0, bl1, bl2, bl3, ahb + AF_BL + bo);
#pragma unroll
            for (int tt = 0; tt < 2; tt++) {
                float* cA = acc[tt][ng];
                float* cB = acc[tt][ng] + 4;
                mma16816(cA, ah[tt], bh0, bh1);
                mma16816(cA, ah[tt], bl0, bl1);
                mma16816(cA, al[tt], bh0, bh1);
                mma16816(cB, ah[tt], bh2, bh3);
                mma16816(cB, ah[tt], bl2, bl3);
                mma16816(cB, al[tt], bh2, bh3);
            }
        }
    }

    // epilogue: stage tile in smem (pitch 132 keeps float4 alignment), write coalesced
    __syncthreads();   // all ldsm reads done; safe to reuse smem
    float (*ts)[132] = (float(*)[132])sm;
#pragma unroll
    for (int tt = 0; tt < 2; tt++) {
        int ml0 = wm * 32 + tt * 16 + (lane >> 2);
#pragma unroll
        for (int ng = 0; ng < 4; ng++) {
            int nl = wn * 64 + ng * 16 + (lane & 3) * 2;
            float* cA = acc[tt][ng];
            ts[ml0][nl] = cA[0];     ts[ml0][nl + 1] = cA[1];
            ts[ml0 + 8][nl] = cA[2]; ts[ml0 + 8][nl + 1] = cA[3];
            ts[ml0][nl + 8] = cA[4]; ts[ml0][nl + 9] = cA[5];
            ts[ml0 + 8][nl + 8] = cA[6]; ts[ml0 + 8][nl + 9] = cA[7];
        }
    }
    __syncthreads();
    float* Ab = A_out + (size_t)b * NN * NN;
    int rr = tid >> 2, qq = (tid & 3) * 32;
#pragma unroll
    for (int pass = 0; pass < 2; pass++) {
        int m = pass * 64 + rr;
        float4* dst = (float4*)&Ab[(size_t)(mbase + m) * NN + nbase + qq];
#pragma unroll
        for (int j = 0; j < 8; j++) dst[j] = *(const float4*)&ts[m][qq + j * 4];
    }
    if (t == 2) {
#pragma unroll
        for (int pass = 0; pass < 2; pass++) {
            int n = pass * 64 + rr;
            float4* dst = (float4*)&Ab[(size_t)(nbase + n) * NN + mbase + qq];
#pragma unroll
            for (int j = 0; j < 8; j++) {
                float4 v4;
                v4.x = ts[qq + j * 4 + 0][n];
                v4.y = ts[qq + j * 4 + 1][n];
                v4.z = ts[qq + j * 4 + 2][n];
                v4.w = ts[qq + j * 4 + 3][n];
                dst[j] = v4;
            }
        }
    }
}

// ---------------- merged stats+loss: one A pass, per-batch spin barrier ----------------
__global__ void __launch_bounds__(256) k_sl(const float* __restrict__ A_out,
                                            float* __restrict__ out_loss) {
    __shared__ float s1[8][32], s2[8][32];
    __shared__ bool is_last;
    int b = blockIdx.x, ib = blockIdx.y * 32;
    int ti = threadIdx.x & 31, ks = threadIdx.x >> 5;
    int i = ib + ti;
    const float* Ab = A_out + (size_t)b * NN * NN;

    uint32_t w1 = g_M1T[b * 2048 + ks * 256 + i];
    uint32_t w2 = g_M2T[b * 2048 + ks * 256 + i];
    if (ks == (i >> 5)) {
        uint32_t d = ~(1u << (i & 31));
        w1 &= d; w2 &= d;
    }
    float ec[32];
    float a1 = 0.f, a2 = 0.f;
#pragma unroll
    for (int kk = 0; kk < 32; kk++) {
        float e = __expf(TEMP * Ab[(size_t)(ks * 32 + kk) * NN + i]);
        ec[kk] = e;
        a1 += ((w1 >> kk) & 1u) ? e : 0.f;
        a2 += ((w2 >> kk) & 1u) ? e : 0.f;
    }
    s1[ks][ti] = a1; s2[ks][ti] = a2;
    __syncthreads();
    if (ks == 0) {
        float W1 = 0.f, W2 = 0.f;
#pragma unroll
        for (int w = 0; w < 8; w++) { W1 += s1[w][ti]; W2 += s2[w][ti]; }
        g_F1[b * NN + i] = 1.0f / fmaxf(2.0f * W1, 1e-30f);
        g_F2[b * NN + i] = 1.0f / fmaxf(2.0f * W2, 1e-30f);
    }
    __threadfence();
    __syncthreads();
    if (threadIdx.x == 0) {
        atomicAdd(&g_bat[b], 1u);
        volatile unsigned int* pb = &g_bat[b];
        while (*pb < 8u) { }
    }
    __syncthreads();
    __threadfence();

    uint32_t wm = g_M1T[b * 2048 + ks * 256 + i] & g_M2R[b * 2048 + ks * 256 + i];
    if (ks == (i >> 5)) wm &= ~(1u << (i & 31));
    float acc = 0.f;
#pragma unroll
    for (int kk = 0; kk < 32; kk++) {
        int k = ks * 32 + kk;
        float t = ec[kk] * ec[kk] * g_F2[b * NN + k];
        acc += ((wm >> kk) & 1u) ? t : 0.f;
    }
    s1[ks][ti] = acc;
    __syncthreads();
    if (threadIdx.x < 32) {
        float v = 0.f;
#pragma unroll
        for (int w = 0; w < 8; w++) v += s1[w][ti];
        v *= 4.0f * g_F1[b * NN + i];
#pragma unroll
        for (int o = 16; o > 0; o >>= 1) v += __shfl_xor_sync(0xffffffffu, v, o);
        if (ti == 0) g_lp2[b * 8 + blockIdx.y] = v;
    }
    __threadfence();
    __syncthreads();
    if (threadIdx.x == 0)
        is_last = (atomicAdd(&g_ctr, 1u) == NBATCH * 8 - 1);
    __syncthreads();
    if (is_last) {
        __shared__ float sr[8];
        int t = threadIdx.x;
        float v = g_lp2[t];
#pragma unroll
        for (int o = 16; o > 0; o >>= 1) v += __shfl_xor_sync(0xffffffffu, v, o);
        if ((t & 31) == 0) sr[t >> 5] = v;
        __syncthreads();
        if (t == 0) {
            float s = 0.f;
#pragma unroll
            for (int w = 0; w < 8; w++) s += sr[w];
            out_loss[0] = -s / (float)(NBATCH * NN);
        }
    }
}

// ---------------- launch ----------------
extern "C" void kernel_launch(void* const* d_in, const int* in_sizes, int n_in,
                              void* d_out, int out_size) {
    const float* x      = (const float*)d_in[0];
    const float* conv_w = (const float*)d_in[1];
    const float* conv_b = (const float*)d_in[2];
    const float* fc1_w  = (const float*)d_in[3];
    const float* fc1_b  = (const float*)d_in[4];
    const float* drop1  = (const float*)d_in[5];
    const float* drop2  = (const float*)d_in[6];
    float* out_f = (float*)d_out;
    float* out_A = out_f + (size_t)BN * VDIM;
    float* out_loss = out_A + (size_t)NBATCH * NN * NN;

    cudaFuncSetAttribute(k_gemm_mma, cudaFuncAttributeMaxDynamicSharedMemorySize, SM_TOTAL_MMA);
    cudaFuncSetAttribute(k_aff, cudaFuncAttributeMaxDynamicSharedMemorySize, SM_TOTAL_AFF);

    k_front<<<257, 256>>>(fc1_w, conv_b, fc1_b, drop1, drop2);
    k_wc_gemm<<<dim3(24, 4), 256>>>(conv_w, fc1_w);
    k_gemm_mma<<<dim3(128, 2), 256, SM_TOTAL_MMA>>>(x, out_f);
    k_aff<<<dim3(3, NBATCH), 256, SM_TOTAL_AFF>>>(out_A);
    k_sl<<<dim3(NBATCH, 8), 256>>>(out_A, out_loss);
}

// round 17
// speedup vs baseline: 1.0829x; 1.0829x over previous
#include <cuda_runtime.h>
#include <cuda_bf16.h>
#include <cstdint>
#include <cstddef>

typedef unsigned long long u64;

#define KDIM 3072
#define FDIM 512
#define VDIM 128
#define NBATCH 32
#define NN 256
#define BN 8192
#define TEMP 11.3137084989847606f  // sqrt(128)

// ---------------- device scratch ----------------
static __device__ float g_fc1T[FDIM * VDIM];
static __device__ float g_bc[VDIM];
static __device__ float g_wcp[4][KDIM * VDIM];
static __device__ __nv_bfloat16 g_Wc_hi[(size_t)VDIM * KDIM];   // [v][k]
static __device__ __nv_bfloat16 g_Wc_lo[(size_t)VDIM * KDIM];   // [v][k]
static __device__ float g_vp[2][(size_t)BN * VDIM];
static __device__ __nv_bfloat16 g_fnh[(size_t)BN * VDIM];       // fn hi (bf16)
static __device__ __nv_bfloat16 g_fnl[(size_t)BN * VDIM];       // fn lo (bf16)
static __device__ uint32_t g_M1T[NBATCH * 8 * NN];  // bit j = d1[b][(kw*32+j)*NN+i] != 0
static __device__ uint32_t g_M2T[NBATCH * 8 * NN];  // bit j = d2[b][(kw*32+j)*NN+i] != 0
static __device__ uint32_t g_M2R[NBATCH * 8 * NN];  // bit j = d2[b][i*NN + kw*32+j] != 0
static __device__ float g_F1[NBATCH * NN];
static __device__ float g_F2[NBATCH * NN];
static __device__ float g_lp2[NBATCH * 8];
static __device__ unsigned int g_cmb[128];          // per-M-tile combine counters
static __device__ unsigned int g_bat[NBATCH];       // per-batch stats barrier
static __device__ unsigned int g_ctr;               // loss final counter

// ---------------- packed f32x2 helpers (SIMT GEMMs) ----------------
__device__ __forceinline__ u64 splat2(float a) {
    u64 r; asm("mov.b64 %0,{%1,%1};" : "=l"(r) : "f"(a)); return r;
}
__device__ __forceinline__ void ffma2(u64& c, u64 a, u64 b) {
    asm("fma.rn.f32x2 %0,%1,%2,%0;" : "+l"(c) : "l"(a), "l"(b));
}
__device__ __forceinline__ float2 unpack2(u64 c) {
    float2 r; asm("mov.b64 {%0,%1},%2;" : "=f"(r.x), "=f"(r.y) : "l"(c)); return r;
}

// ---------------- mma.sync helpers (plain PTX, sm_80+) ----------------
__device__ __forceinline__ uint32_t smem_u32(const void* p) {
    uint32_t a;
    asm("{ .reg .u64 t; cvta.to.shared.u64 t, %1; cvt.u32.u64 %0, t; }" : "=r"(a) : "l"(p));
    return a;
}
__device__ __forceinline__ uint32_t swz(uint32_t o) { return o ^ ((o >> 3) & 0x70); }

__device__ __forceinline__ void ldsm4(uint32_t& r0, uint32_t& r1, uint32_t& r2, uint32_t& r3,
                                      uint32_t addr) {
    asm volatile("ldmatrix.sync.aligned.m8n8.x4.shared.b16 {%0,%1,%2,%3}, [%4];"
                 : "=r"(r0), "=r"(r1), "=r"(r2), "=r"(r3) : "r"(addr));
}
__device__ __forceinline__ void mma16816(float* c, const uint32_t* a, uint32_t b0, uint32_t b1) {
    asm volatile("mma.sync.aligned.m16n8k16.row.col.f32.bf16.bf16.f32 "
                 "{%0,%1,%2,%3}, {%4,%5,%6,%7}, {%8,%9}, {%0,%1,%2,%3};"
                 : "+f"(c[0]), "+f"(c[1]), "+f"(c[2]), "+f"(c[3])
                 : "r"(a[0]), "r"(a[1]), "r"(a[2]), "r"(a[3]), "r"(b0), "r"(b1));
}
__device__ __forceinline__ void cp16(uint32_t saddr, const void* gptr) {
    asm volatile("cp.async.cg.shared.global [%0], [%1], 16;"
                 :: "r"(saddr), "l"(__cvta_generic_to_global(gptr)) : "memory");
}
__device__ __forceinline__ void cp_commit() {
    asm volatile("cp.async.commit_group;" ::: "memory");
}
__device__ __forceinline__ void cp_wait0() {
    asm volatile("cp.async.wait_group 0;" ::: "memory");
}

// ---------------- front: fc1 transpose + folded bias + mask packing (ballot M2R) ----------------
// grid 513: [0,256) fc1T, 256 = bc + counters, [257,513) packing (one block per (batch, kw))
__global__ void __launch_bounds__(256) k_front(const float* __restrict__ fc1_w,
                                               const float* __restrict__ conv_b,
                                               const float* __restrict__ fc1_b,
                                               const float* __restrict__ d1,
                                               const float* __restrict__ d2) {
    int bid = blockIdx.x;
    if (bid < 256) {
        int idx = bid * 256 + threadIdx.x;          // 65536
        int o = idx >> 7, v = idx & 127;
        g_fc1T[idx] = fc1_w[v * FDIM + o];
    } else if (bid == 256) {
        int v = threadIdx.x;
        if (v < 128) {
            float s = fc1_b[v];
            for (int o = 0; o < FDIM; o++) s += fc1_w[v * FDIM + o] * conv_b[o];
            g_bc[v] = s;
            g_cmb[v] = 0;
        } else if (v < 160) {
            g_bat[v - 128] = 0;
        } else if (v == 160) {
            g_ctr = 0;
        }
    } else {
        int idx2 = bid - 257;                        // 0..255
        int b = idx2 >> 3, kw = idx2 & 7;
        int i = threadIdx.x;                         // 0..255 (column)
        int lane = i & 31, w = i >> 5;
        const float* D1 = d1 + (size_t)b * NN * NN;
        const float* D2 = d2 + (size_t)b * NN * NN;
        uint32_t m1 = 0, m2 = 0;
#pragma unroll 8
        for (int j = 0; j < 32; j++) {
            size_t off = (size_t)(kw * 32 + j) * NN + i;
            m1 |= (D1[off] != 0.0f ? 1u : 0u) << j;
            m2 |= (D2[off] != 0.0f ? 1u : 0u) << j;
        }
        g_M1T[b * 2048 + kw * 256 + i] = m1;
        g_M2T[b * 2048 + kw * 256 + i] = m2;
        // M2R via warp-ballot bit-transpose of the column-pack words (no second d2 read).
        // Warp w covers columns w*32..w*32+31; ballot of bit jj yields the word whose
        // bit l = d2[(kw*32+jj)][w*32+l]  ->  M2R[b][kw'=w][i' = kw*32+jj].
        uint32_t mine = 0;
#pragma unroll
        for (int jj = 0; jj < 32; jj++) {
            uint32_t bal = __ballot_sync(0xffffffffu, (m2 >> jj) & 1u);
            if (lane == jj) mine = bal;
        }
        g_M2R[b * 2048 + w * 256 + kw * 32 + lane] = mine;
    }
}

// ---------------- Wc GEMM: part[k3][v] = sum_o conv_w[o][k3]*fc1T[o][v], split-K 4 ----------------
__global__ void __launch_bounds__(256) k_wc_gemm(const float* __restrict__ conv_w) {
    __shared__ float As[2][16][128];
    __shared__ float Bs[2][16][128];
    int tid = threadIdx.x;
    int mb = blockIdx.x * 128;
    int ks = blockIdx.y;
    int tx = tid & 15, ty = tid >> 4;
    int lo = tid >> 5, lq = tid & 31;
    const float* gA = conv_w + (size_t)(ks * 128) * KDIM + mb;
    const float* gB = g_fc1T + (size_t)(ks * 128) * VDIM;
    float4 pa0, pa1, pb0, pb1;
    auto loadG = [&](int it) {
        pa0 = *(const float4*)(gA + (size_t)(it * 16 + lo) * KDIM + lq * 4);
        pa1 = *(const float4*)(gA + (size_t)(it * 16 + lo + 8) * KDIM + lq * 4);
        pb0 = *(const float4*)(gB + (it * 16 + lo) * VDIM + lq * 4);
        pb1 = *(const float4*)(gB + (it * 16 + lo + 8) * VDIM + lq * 4);
    };
    auto storeS = [&](int buf) {
        *(float4*)&As[buf][lo][lq * 4] = pa0;
        *(float4*)&As[buf][lo + 8][lq * 4] = pa1;
        *(float4*)&Bs[buf][lo][lq * 4] = pb0;
        *(float4*)&Bs[buf][lo + 8][lq * 4] = pb1;
    };
    loadG(0); storeS(0); __syncthreads();
    u64 c[32];
#pragma unroll
    for (int i = 0; i < 32; i++) c[i] = 0ull;
    const int NIT = 8;   // 128 o's / 16
    for (int it = 0; it < NIT; ++it) {
        int cur = it & 1;
        if (it + 1 < NIT) loadG(it + 1);
#pragma unroll
        for (int kk = 0; kk < 16; kk++) {
            float4 af0 = *(float4*)&As[cur][kk][ty * 8];
            float4 af1 = *(float4*)&As[cur][kk][ty * 8 + 4];
            float4 bf0 = *(float4*)&Bs[cur][kk][tx * 8];
            float4 bf1 = *(float4*)&Bs[cur][kk][tx * 8 + 4];
            u64 b[4] = { *(u64*)&bf0.x, *(u64*)&bf0.z, *(u64*)&bf1.x, *(u64*)&bf1.z };
            float a[8] = { af0.x, af0.y, af0.z, af0.w, af1.x, af1.y, af1.z, af1.w };
#pragma unroll
            for (int mi = 0; mi < 8; mi++) {
                u64 as = splat2(a[mi]);
#pragma unroll
                for (int p = 0; p < 4; p++) ffma2(c[mi * 4 + p], as, b[p]);
            }
        }
        if (it + 1 < NIT) { storeS((it + 1) & 1); __syncthreads(); }
    }
    float* out = g_wcp[ks];
#pragma unroll
    for (int mi = 0; mi < 8; mi++) {
        float2* orow = (float2*)(out + (size_t)(mb + ty * 8 + mi) * VDIM);
#pragma unroll
        for (int p = 0; p < 4; p++) orow[tx * 4 + p] = unpack2(c[mi * 4 + p]);
    }
}

// combine 4 split-K partials, transpose to [v][k], convert to bf16 hi/lo
__global__ void __launch_bounds__(256) k_wc_finish() {
    __shared__ float ts[16][129];
    int k0 = blockIdx.x * 16;
    int t = threadIdx.x;
#pragma unroll
    for (int j = 0; j < 8; j++) {
        int idx = t + 256 * j;                       // 2048
        int kk = idx >> 7, v = idx & 127;
        size_t o = (size_t)(k0 + kk) * 128 + v;
        float s = (g_wcp[0][o] + g_wcp[1][o]) + (g_wcp[2][o] + g_wcp[3][o]);
        ts[kk][v] = s;
    }
    __syncthreads();
#pragma unroll
    for (int j = 0; j < 8; j++) {
        int idx = t + 256 * j;
        int v = idx >> 4, kk = idx & 15;
        float val = ts[kk][v];
        __nv_bfloat16 h = __float2bfloat16(val);
        __nv_bfloat16 l = __float2bfloat16(val - __bfloat162float(h));
        g_Wc_hi[(size_t)v * KDIM + k0 + kk] = h;
        g_Wc_lo[(size_t)v * KDIM + k0 + kk] = l;
    }
}

// ---------------- main GEMM + fused combine/normalize epilogue ----------------
#define SMA_L 8192
#define SMB_H 16384
#define SMB_L 32768
#define BUFSZ 49152
#define SM_TOTAL_MMA (2 * BUFSZ)

__global__ void __launch_bounds__(256, 2) k_gemm_mma(const float* __restrict__ X,
                                                     float* __restrict__ f_out) {
    extern __shared__ __align__(128) char sm[];
    int tid = threadIdx.x;
    int warp = tid >> 5, lane = tid & 31;
    int wm = warp >> 2, wn = warp & 3;
    int mb = blockIdx.x * 64;
    int ksOff = blockIdx.y * 1536;
    const float* gX = X + (size_t)mb * KDIM + ksOff;

    float acc[2][2][8];
#pragma unroll
    for (int t = 0; t < 2; t++)
#pragma unroll
        for (int n = 0; n < 2; n++)
#pragma unroll
            for (int p = 0; p < 8; p++) acc[t][n][p] = 0.f;

    int aRow = tid >> 2, aQ = tid & 3;
    float4 pa[4];

    auto loadA = [&](int c) {
#pragma unroll
        for (int j = 0; j < 4; j++)
            pa[j] = *(const float4*)(gX + (size_t)aRow * KDIM + c * 64 + aQ * 16 + j * 4);
    };
    auto storeA = [&](int s) {
        char* base = sm + s * BUFSZ;
#pragma unroll
        for (int j = 0; j < 4; j++) {
            float4 v = pa[j];
            __nv_bfloat16 h0 = __float2bfloat16(v.x), h1 = __float2bfloat16(v.y);
            __nv_bfloat16 h2 = __float2bfloat16(v.z), h3 = __float2bfloat16(v.w);
            __nv_bfloat16 l0 = __float2bfloat16(v.x - __bfloat162float(h0));
            __nv_bfloat16 l1 = __float2bfloat16(v.y - __bfloat162float(h1));
            __nv_bfloat16 l2 = __float2bfloat16(v.z - __bfloat162float(h2));
            __nv_bfloat16 l3 = __float2bfloat16(v.w - __bfloat162float(h3));
            uint32_t hw0 = (uint32_t)__bfloat16_as_ushort(h0) | ((uint32_t)__bfloat16_as_ushort(h1) << 16);
            uint32_t hw1 = (uint32_t)__bfloat16_as_ushort(h2) | ((uint32_t)__bfloat16_as_ushort(h3) << 16);
            uint32_t lw0 = (uint32_t)__bfloat16_as_ushort(l0) | ((uint32_t)__bfloat16_as_ushort(l1) << 16);
            uint32_t lw1 = (uint32_t)__bfloat16_as_ushort(l2) | ((uint32_t)__bfloat16_as_ushort(l3) << 16);
            uint32_t off = swz((uint32_t)(aRow * 128 + aQ * 32 + j * 8));
            *(uint2*)(base + off) = make_uint2(hw0, hw1);
            *(uint2*)(base + SMA_L + off) = make_uint2(lw0, lw1);
        }
    };
    int bRow = tid >> 1, bQ = tid & 1;
    auto issueB = [&](int c, int s) {
        char* base = sm + s * BUFSZ;
        size_t gbyte = ((size_t)bRow * KDIM + ksOff + c * 64) * 2;
#pragma unroll
        for (int j = 0; j < 4; j++) {
            int colb = (bQ * 4 + j) * 16;
            uint32_t off = swz((uint32_t)(bRow * 128 + colb));
            cp16(smem_u32(base + SMB_H + off), (const char*)g_Wc_hi + gbyte + colb);
            cp16(smem_u32(base + SMB_L + off), (const char*)g_Wc_lo + gbyte + colb);
        }
    };

    issueB(0, 0); cp_commit();
    loadA(0); storeA(0);
    cp_wait0();
    __syncthreads();

    int aLn = lane & 15, aLu = (lane >> 4) & 1;
    int bLn = (lane & 7) + ((lane >> 4) & 1) * 8;
    int bLu = (lane >> 3) & 1;

    const int NCH = 24;
    for (int c = 0; c < NCH; c++) {
        int s = c & 1;
        if (c + 1 < NCH) { issueB(c + 1, s ^ 1); cp_commit(); loadA(c + 1); }
        uint32_t baseA_h = smem_u32(sm + s * BUFSZ);
        uint32_t baseA_l = baseA_h + SMA_L;
        uint32_t baseB_h = baseA_h + SMB_H;
        uint32_t baseB_l = baseA_h + SMB_L;
#pragma unroll
        for (int kst = 0; kst < 4; kst++) {
            uint32_t ah[2][4], al[2][4];
#pragma unroll
            for (int t = 0; t < 2; t++) {
                uint32_t aOff = swz((uint32_t)((wm * 32 + t * 16 + aLn) * 128 + kst * 32 + aLu * 16));
                ldsm4(ah[t][0], ah[t][1], ah[t][2], ah[t][3], baseA_h + aOff);
                ldsm4(al[t][0], al[t][1], al[t][2], al[t][3], baseA_l + aOff);
            }
#pragma unroll
            for (int nt = 0; nt < 2; nt++) {
                uint32_t bh0, bh1, bh2, bh3, bl0, bl1, bl2, bl3;
                uint32_t bo = swz((uint32_t)((wn * 32 + nt * 16 + bLn) * 128 + kst * 32 + bLu * 16));
                ldsm4(bh0, bh1, bh2, bh3, baseB_h + bo);
                ldsm4(bl0, bl1, bl2, bl3, baseB_l + bo);
#pragma unroll
                for (int t = 0; t < 2; t++) {
                    float* cA = acc[t][nt];
                    float* cB = acc[t][nt] + 4;
                    mma16816(cA, ah[t], bh0, bh1);
                    mma16816(cA, ah[t], bl0, bl1);
                    mma16816(cA, al[t], bh0, bh1);
                    mma16816(cB, ah[t], bh2, bh3);
                    mma16816(cB, ah[t], bl2, bl3);
                    mma16816(cB, al[t], bh2, bh3);
                }
            }
        }
        if (c + 1 < NCH) { storeA(s ^ 1); cp_wait0(); __syncthreads(); }
    }

    // write split-K partials
#pragma unroll
    for (int t = 0; t < 2; t++) {
        int m0 = mb + wm * 32 + t * 16 + (lane >> 2);
        float* o0 = g_vp[blockIdx.y] + (size_t)m0 * VDIM;
#pragma unroll
        for (int nt = 0; nt < 2; nt++) {
            int n = wn * 32 + nt * 16 + (lane & 3) * 2;
            *(float2*)(o0 + n) = make_float2(acc[t][nt][0], acc[t][nt][1]);
            *(float2*)(o0 + 8 * VDIM + n) = make_float2(acc[t][nt][2], acc[t][nt][3]);
            *(float2*)(o0 + n + 8) = make_float2(acc[t][nt][4], acc[t][nt][5]);
            *(float2*)(o0 + 8 * VDIM + n + 8) = make_float2(acc[t][nt][6], acc[t][nt][7]);
        }
    }

    // fused combine: second-finishing CTA sums partials + bias, normalizes, emits fn as bf16 hi/lo
    __threadfence();
    __shared__ unsigned int rank_sh;
    if (tid == 0) rank_sh = atomicAdd(&g_cmb[blockIdx.x], 1u);
    __syncthreads();
    if (rank_sh == 1) {
        __threadfence();   // acquire: other CTA's partial writes are visible
        const float4 bc = *(const float4*)&g_bc[lane * 4];
#pragma unroll
        for (int r = 0; r < 8; r++) {
            int row = mb + warp * 8 + r;
            size_t base = (size_t)row * VDIM + lane * 4;
            float4 p0 = *(const float4*)&g_vp[0][base];
            float4 p1 = *(const float4*)&g_vp[1][base];
            float4 x;
            x.x = p0.x + p1.x + bc.x;
            x.y = p0.y + p1.y + bc.y;
            x.z = p0.z + p1.z + bc.z;
            x.w = p0.w + p1.w + bc.w;
            *(float4*)&f_out[base] = x;
            float ss = x.x * x.x + x.y * x.y + x.z * x.z + x.w * x.w;
#pragma unroll
            for (int o = 16; o > 0; o >>= 1) ss += __shfl_xor_sync(0xffffffffu, ss, o);
            float inv = 1.0f / fmaxf(sqrtf(ss), 1e-12f);
            x.x *= inv; x.y *= inv; x.z *= inv; x.w *= inv;
            __nv_bfloat16 h0 = __float2bfloat16(x.x), h1 = __float2bfloat16(x.y);
            __nv_bfloat16 h2 = __float2bfloat16(x.z), h3 = __float2bfloat16(x.w);
            __nv_bfloat16 l0 = __float2bfloat16(x.x - __bfloat162float(h0));
            __nv_bfloat16 l1 = __float2bfloat16(x.y - __bfloat162float(h1));
            __nv_bfloat16 l2 = __float2bfloat16(x.z - __bfloat162float(h2));
            __nv_bfloat16 l3 = __float2bfloat16(x.w - __bfloat162float(h3));
            uint32_t hw0 = (uint32_t)__bfloat16_as_ushort(h0) | ((uint32_t)__bfloat16_as_ushort(h1) << 16);
            uint32_t hw1 = (uint32_t)__bfloat16_as_ushort(h2) | ((uint32_t)__bfloat16_as_ushort(h3) << 16);
            uint32_t lw0 = (uint32_t)__bfloat16_as_ushort(l0) | ((uint32_t)__bfloat16_as_ushort(l1) << 16);
            uint32_t lw1 = (uint32_t)__bfloat16_as_ushort(l2) | ((uint32_t)__bfloat16_as_ushort(l3) << 16);
            *(uint2*)&g_fnh[base] = make_uint2(hw0, hw1);
            *(uint2*)&g_fnl[base] = make_uint2(lw0, lw1);
        }
    }
}

// ---------------- affinity via mma.sync: A[b] = fn fn^T (symmetric, bf16 hi/lo 3-product) ----------------
// grid (3, 32), 256 threads, 8 warps (4 wm x 2 wn), warp tile 32x64. K=128 in 2 chunk regions.
#define AF_AL 32768
#define AF_BH 65536
#define AF_BL 98304
#define SM_TOTAL_AFF 131072

__global__ void __launch_bounds__(256, 1) k_aff(float* __restrict__ A_out) {
    extern __shared__ __align__(128) char sm[];
    int t = blockIdx.x;                  // 0:(0,0) 1:(1,1) 2:(0,1)+mirror
    int b = blockIdx.y;
    int mbase = (t == 1) ? 128 : 0;
    int nbase = (t == 0) ? 0 : 128;
    int tid = threadIdx.x, warp = tid >> 5, lane = tid & 31;
    int wm = warp >> 1, wn = warp & 1;
    const __nv_bfloat16* fh = g_fnh + (size_t)b * NN * VDIM;
    const __nv_bfloat16* fl = g_fnl + (size_t)b * NN * VDIM;

    {
        int row = tid >> 1, ch = tid & 1;
        const uint4* sAh = (const uint4*)(fh + (size_t)(mbase + row) * VDIM + ch * 64);
        const uint4* sAl = (const uint4*)(fl + (size_t)(mbase + row) * VDIM + ch * 64);
        const uint4* sBh = (const uint4*)(fh + (size_t)(nbase + row) * VDIM + ch * 64);
        const uint4* sBl = (const uint4*)(fl + (size_t)(nbase + row) * VDIM + ch * 64);
#pragma unroll
        for (int j = 0; j < 8; j++) {
            uint32_t off = (uint32_t)(ch * 16384) + swz((uint32_t)(row * 128 + j * 16));
            *(uint4*)(sm + off) = sAh[j];
            *(uint4*)(sm + AF_AL + off) = sAl[j];
            *(uint4*)(sm + AF_BH + off) = sBh[j];
            *(uint4*)(sm + AF_BL + off) = sBl[j];
        }
    }
    __syncthreads();

    float acc[2][4][8];
#pragma unroll
    for (int tt = 0; tt < 2; tt++)
#pragma unroll
        for (int n = 0; n < 4; n++)
#pragma unroll
            for (int p = 0; p < 8; p++) acc[tt][n][p] = 0.f;

    uint32_t ahb = smem_u32(sm);
    int aLn = lane & 15, aLu = (lane >> 4) & 1;
    int bLn = (lane & 7) + ((lane >> 4) & 1) * 8;
    int bLu = (lane >> 3) & 1;

#pragma unroll
    for (int kst = 0; kst < 8; kst++) {
        uint32_t chOff = (uint32_t)((kst >> 2) * 16384);
        int kk = kst & 3;
        uint32_t ah[2][4], al[2][4];
#pragma unroll
        for (int tt = 0; tt < 2; tt++) {
            uint32_t aOff = chOff + swz((uint32_t)((wm * 32 + tt * 16 + aLn) * 128 + kk * 32 + aLu * 16));
            ldsm4(ah[tt][0], ah[tt][1], ah[tt][2], ah[tt][3], ahb + aOff);
            ldsm4(al[tt][0], al[tt][1], al[tt][2], al[tt][3], ahb + AF_AL + aOff);
        }
#pragma unroll
        for (int ng = 0; ng < 4; ng++) {
            uint32_t bo = chOff + swz((uint32_t)((wn * 64 + ng * 16 + bLn) * 128 + kk * 32 + bLu * 16));
            uint32_t bh0, bh1, bh2, bh3, bl0, bl1, bl2, bl3;
            ldsm4(bh0, bh1, bh2, bh3, ahb + AF_BH + bo);
            ldsm4(bl0, bl1, bl2, bl3, ahb + AF_BL + bo);
#pragma unroll
            for (int tt = 0; tt < 2; tt++) {
                float* cA = acc[tt][ng];
                float* cB = acc[tt][ng] + 4;
                mma16816(cA, ah[tt], bh0, bh1);
                mma16816(cA, ah[tt], bl0, bl1);
                mma16816(cA, al[tt], bh0, bh1);
                mma16816(cB, ah[tt], bh2, bh3);
                mma16816(cB, ah[tt], bl2, bl3);
                mma16816(cB, al[tt], bh2, bh3);
            }
        }
    }

    float* Ab = A_out + (size_t)b * NN * NN;
#pragma unroll
    for (int tt = 0; tt < 2; tt++) {
        int m0 = mbase + wm * 32 + tt * 16 + (lane >> 2);
#pragma unroll
        for (int ng = 0; ng < 4; ng++) {
            int n = nbase + wn * 64 + ng * 16 + (lane & 3) * 2;
            float* cA = acc[tt][ng];
            *(float2*)&Ab[(size_t)m0 * NN + n] = make_float2(cA[0], cA[1]);
            *(float2*)&Ab[(size_t)(m0 + 8) * NN + n] = make_float2(cA[2], cA[3]);
            *(float2*)&Ab[(size_t)m0 * NN + n + 8] = make_float2(cA[4], cA[5]);
            *(float2*)&Ab[(size_t)(m0 + 8) * NN + n + 8] = make_float2(cA[6], cA[7]);
            if (t == 2) {
                Ab[(size_t)n * NN + m0] = cA[0];
                Ab[(size_t)(n + 1) * NN + m0] = cA[1];
                Ab[(size_t)n * NN + m0 + 8] = cA[2];
                Ab[(size_t)(n + 1) * NN + m0 + 8] = cA[3];
                Ab[(size_t)(n + 8) * NN + m0] = cA[4];
                Ab[(size_t)(n + 9) * NN + m0] = cA[5];
                Ab[(size_t)(n + 8) * NN + m0 + 8] = cA[6];
                Ab[(size_t)(n + 9) * NN + m0 + 8] = cA[7];
            }
        }
    }
}

// ---------------- merged stats+loss: one A pass, per-batch spin barrier ----------------
__global__ void __launch_bounds__(256) k_sl(const float* __restrict__ A_out,
                                            float* __restrict__ out_loss) {
    __shared__ float s1[8][32], s2[8][32];
    __shared__ bool is_last;
    int b = blockIdx.x, ib = blockIdx.y * 32;
    int ti = threadIdx.x & 31, ks = threadIdx.x >> 5;
    int i = ib + ti;
    const float* Ab = A_out + (size_t)b * NN * NN;

    uint32_t w1 = g_M1T[b * 2048 + ks * 256 + i];
    uint32_t w2 = g_M2T[b * 2048 + ks * 256 + i];
    if (ks == (i >> 5)) {
        uint32_t d = ~(1u << (i & 31));
        w1 &= d; w2 &= d;
    }
    float ec[32];
    float a1 = 0.f, a2 = 0.f;
#pragma unroll
    for (int kk = 0; kk < 32; kk++) {
        float e = __expf(TEMP * Ab[(size_t)(ks * 32 + kk) * NN + i]);
        ec[kk] = e;
        a1 += ((w1 >> kk) & 1u) ? e : 0.f;
        a2 += ((w2 >> kk) & 1u) ? e : 0.f;
    }
    s1[ks][ti] = a1; s2[ks][ti] = a2;
    __syncthreads();
    if (ks == 0) {
        float W1 = 0.f, W2 = 0.f;
#pragma unroll
        for (int w = 0; w < 8; w++) { W1 += s1[w][ti]; W2 += s2[w][ti]; }
        g_F1[b * NN + i] = 1.0f / fmaxf(2.0f * W1, 1e-30f);
        g_F2[b * NN + i] = 1.0f / fmaxf(2.0f * W2, 1e-30f);
    }
    __threadfence();
    __syncthreads();
    if (threadIdx.x == 0) {
        atomicAdd(&g_bat[b], 1u);
        volatile unsigned int* pb = &g_bat[b];
        while (*pb < 8u) { }
    }
    __syncthreads();
    __threadfence();

    uint32_t wm = g_M1T[b * 2048 + ks * 256 + i] & g_M2R[b * 2048 + ks * 256 + i];
    if (ks == (i >> 5)) wm &= ~(1u << (i & 31));
    float acc = 0.f;
#pragma unroll
    for (int kk = 0; kk < 32; kk++) {
        int k = ks * 32 + kk;
        float t = ec[kk] * ec[kk] * g_F2[b * NN + k];
        acc += ((wm >> kk) & 1u) ? t : 0.f;
    }
    s1[ks][ti] = acc;
    __syncthreads();
    if (threadIdx.x < 32) {
        float v = 0.f;
#pragma unroll
        for (int w = 0; w < 8; w++) v += s1[w][ti];
        v *= 4.0f * g_F1[b * NN + i];
#pragma unroll
        for (int o = 16; o > 0; o >>= 1) v += __shfl_xor_sync(0xffffffffu, v, o);
        if (ti == 0) g_lp2[b * 8 + blockIdx.y] = v;
    }
    __threadfence();
    __syncthreads();
    if (threadIdx.x == 0)
        is_last = (atomicAdd(&g_ctr, 1u) == NBATCH * 8 - 1);
    __syncthreads();
    if (is_last) {
        __shared__ float sr[8];
        int t = threadIdx.x;
        float v = g_lp2[t];
#pragma unroll
        for (int o = 16; o > 0; o >>= 1) v += __shfl_xor_sync(0xffffffffu, v, o);
        if ((t & 31) == 0) sr[t >> 5] = v;
        __syncthreads();
        if (t == 0) {
            float s = 0.f;
#pragma unroll
            for (int w = 0; w < 8; w++) s += sr[w];
            out_loss[0] = -s / (float)(NBATCH * NN);
        }
    }
}

// ---------------- launch ----------------
extern "C" void kernel_launch(void* const* d_in, const int* in_sizes, int n_in,
                              void* d_out, int out_size) {
    const float* x      = (const float*)d_in[0];
    const float* conv_w = (const float*)d_in[1];
    const float* conv_b = (const float*)d_in[2];
    const float* fc1_w  = (const float*)d_in[3];
    const float* fc1_b  = (const float*)d_in[4];
    const float* drop1  = (const float*)d_in[5];
    const float* drop2  = (const float*)d_in[6];
    float* out_f = (float*)d_out;
    float* out_A = out_f + (size_t)BN * VDIM;
    float* out_loss = out_A + (size_t)NBATCH * NN * NN;

    cudaFuncSetAttribute(k_gemm_mma, cudaFuncAttributeMaxDynamicSharedMemorySize, SM_TOTAL_MMA);
    cudaFuncSetAttribute(k_aff, cudaFuncAttributeMaxDynamicSharedMemorySize, SM_TOTAL_AFF);

    k_front<<<513, 256>>>(fc1_w, conv_b, fc1_b, drop1, drop2);
    k_wc_gemm<<<dim3(24, 4), 256>>>(conv_w);
    k_wc_finish<<<192, 256>>>();
    k_gemm_mma<<<dim3(128, 2), 256, SM_TOTAL_MMA>>>(x, out_f);
    k_aff<<<dim3(3, NBATCH), 256, SM_TOTAL_AFF>>>(out_A);
    k_sl<<<dim3(NBATCH, 8), 256>>>(out_A, out_loss);
}